// round 1
// baseline (speedup 1.0000x reference)
#include <cuda_runtime.h>
#include <math.h>

// Two double accumulators: [0] = sum of squared diffs for stream 1 (z1,b1),
// [1] = stream 2 (z2,b2). Zeroed by init kernel every launch (graph-safe).
__device__ double g_acc[2];

__global__ void sat_init_kernel() {
    g_acc[0] = 0.0;
    g_acc[1] = 0.0;
}

// Stable softplus: log(1 + e^x)
__device__ __forceinline__ float softplusf(float x) {
    return fmaxf(x, 0.0f) + log1pf(expf(-fabsf(x)));
}

// One warp per (stream,row). blockDim = 256 (8 warps). gridDim = 2N/8.
// Blocks are stream-homogeneous since N % (warps_per_block) == 0.
__global__ void __launch_bounds__(256) sat_main_kernel(
    const int* __restrict__ b1, const int* __restrict__ b2,
    const float* __restrict__ z1, const float* __restrict__ z2,
    const float* __restrict__ g1, const float* __restrict__ g2,
    int N)
{
    const int lane = threadIdx.x & 31;
    const int wib  = threadIdx.x >> 5;                    // warp in block
    const long long warpId = (long long)blockIdx.x * 8 + wib; // 0 .. 2N-1
    const int stream = (warpId >= N) ? 1 : 0;
    const int row = (int)(warpId - (long long)stream * N);

    const int*   b     = stream ? b2 : b1;
    const float* z     = stream ? z2 : z1;
    const float* gSelf = stream ? g2 : g1;  // self pairing: (z1,g1), (z2,g2)
    const float* gCross= stream ? g1 : g2;

    const int gidx = b[row];

    // D = 256 floats = 64 float4 per row; lane loads float4 #lane and #(lane+32)
    const float4* z4  = reinterpret_cast<const float4*>(z) + (long long)row * 64;
    const float4* gs4 = reinterpret_cast<const float4*>(gSelf)  + (long long)gidx * 64;
    const float4* gc4 = reinterpret_cast<const float4*>(gCross) + (long long)gidx * 64;

    float4 za = z4[lane];
    float4 zb = z4[lane + 32];
    float4 sa = gs4[lane];
    float4 sb = gs4[lane + 32];
    float4 ca = gc4[lane];
    float4 cb = gc4[lane + 32];

    float dotS = za.x * sa.x + za.y * sa.y + za.z * sa.z + za.w * sa.w
               + zb.x * sb.x + zb.y * sb.y + zb.z * sb.z + zb.w * sb.w;
    float dotC = za.x * ca.x + za.y * ca.y + za.z * ca.z + za.w * ca.w
               + zb.x * cb.x + zb.y * cb.y + zb.z * cb.z + zb.w * cb.w;

    // warp reduce both dot products
    #pragma unroll
    for (int off = 16; off > 0; off >>= 1) {
        dotS += __shfl_down_sync(0xFFFFFFFFu, dotS, off);
        dotC += __shfl_down_sync(0xFFFFFFFFu, dotC, off);
    }

    __shared__ double s_part[8];
    if (lane == 0) {
        // self_js - cross_js = softplus(-dotC) - softplus(-dotS)  (LOG2 cancels)
        float t = softplusf(-dotC) - softplusf(-dotS);
        s_part[wib] = (double)t * (double)t;
    }
    __syncthreads();

    if (threadIdx.x == 0) {
        double s = 0.0;
        #pragma unroll
        for (int i = 0; i < 8; i++) s += s_part[i];
        atomicAdd(&g_acc[stream], s);
    }
}

__global__ void sat_finish_kernel(float* out) {
    out[0] = (float)(sqrt(g_acc[0]) + sqrt(g_acc[1]));
}

extern "C" void kernel_launch(void* const* d_in, const int* in_sizes, int n_in,
                              void* d_out, int out_size) {
    const int*   b1 = (const int*)d_in[0];
    const int*   b2 = (const int*)d_in[1];
    const float* z1 = (const float*)d_in[2];
    const float* z2 = (const float*)d_in[3];
    const float* g1 = (const float*)d_in[4];
    const float* g2 = (const float*)d_in[5];
    float* out = (float*)d_out;

    const int N = in_sizes[0];              // 65536
    const int warpsPerBlock = 8;            // 256 threads
    const long long totalWarps = 2LL * N;
    const int grid = (int)((totalWarps + warpsPerBlock - 1) / warpsPerBlock);

    sat_init_kernel<<<1, 1>>>();
    sat_main_kernel<<<grid, 256>>>(b1, b2, z1, z2, g1, g2, N);
    sat_finish_kernel<<<1, 1>>>(out);
}

// round 2
// speedup vs baseline: 1.0988x; 1.0988x over previous
#include <cuda_runtime.h>
#include <math.h>

#define ROWS_PER_WARP   16
#define WARPS_PER_BLOCK 8
#define THREADS         (WARPS_PER_BLOCK * 32)
#define MAX_BLOCKS      8192

// Per-block partial sums. Every launch writes every used slot -> no init needed.
__device__ double g_part[MAX_BLOCKS];
// Completion counter: zero at load; last block resets it to 0 each launch,
// so graph replays are deterministic.
__device__ unsigned int g_count;

__device__ __forceinline__ float softplusf(float x) {
    // stable log(1 + e^x)
    return fmaxf(x, 0.0f) + log1pf(expf(-fabsf(x)));
}

__global__ void __launch_bounds__(THREADS) sat_fused_kernel(
    const int* __restrict__ b1, const int* __restrict__ b2,
    const float* __restrict__ z1, const float* __restrict__ z2,
    const float* __restrict__ g1, const float* __restrict__ g2,
    float* __restrict__ out, int N)
{
    const int lane = threadIdx.x & 31;
    const int wib  = threadIdx.x >> 5;

    const int warpsPerStream = N / ROWS_PER_WARP;             // 4096
    const int gwarp  = blockIdx.x * WARPS_PER_BLOCK + wib;    // 0 .. 2*wps-1
    const int stream = (gwarp >= warpsPerStream) ? 1 : 0;
    const int wloc   = gwarp - stream * warpsPerStream;
    const int base   = wloc * ROWS_PER_WARP;                  // first row of chunk

    const int*   b  = stream ? b2 : b1;
    const float* z  = stream ? z2 : z1;
    const float* gS = stream ? g2 : g1;   // self pairing
    const float* gC = stream ? g1 : g2;   // cross pairing

    // One coalesced load of the 16 batch ids for this warp's chunk.
    int myb = (lane < ROWS_PER_WARP) ? b[base + lane] : 0;

    const float4* z4 = reinterpret_cast<const float4*>(z) + (size_t)base * 64;

    double acc = 0.0;
    int cur = -1;
    float4 sa, sb, ca, cb;   // cached g rows (registers)
    sa = sb = ca = cb = make_float4(0.f, 0.f, 0.f, 0.f);

    #pragma unroll 4
    for (int r = 0; r < ROWS_PER_WARP; ++r) {
        const int gidx = __shfl_sync(0xFFFFFFFFu, myb, r);
        if (gidx != cur) {   // warp-uniform branch; rare (sorted batch)
            cur = gidx;
            const float4* gs4 = reinterpret_cast<const float4*>(gS) + (size_t)gidx * 64;
            const float4* gc4 = reinterpret_cast<const float4*>(gC) + (size_t)gidx * 64;
            sa = gs4[lane]; sb = gs4[lane + 32];
            ca = gc4[lane]; cb = gc4[lane + 32];
        }
        const float4* zr = z4 + (size_t)r * 64;
        float4 za = zr[lane];
        float4 zb = zr[lane + 32];

        float dS = za.x*sa.x + za.y*sa.y + za.z*sa.z + za.w*sa.w
                 + zb.x*sb.x + zb.y*sb.y + zb.z*sb.z + zb.w*sb.w;
        float dC = za.x*ca.x + za.y*ca.y + za.z*ca.z + za.w*ca.w
                 + zb.x*cb.x + zb.y*cb.y + zb.z*cb.z + zb.w*cb.w;

        #pragma unroll
        for (int off = 16; off > 0; off >>= 1) {
            dS += __shfl_xor_sync(0xFFFFFFFFu, dS, off);
            dC += __shfl_xor_sync(0xFFFFFFFFu, dC, off);
        }
        if (lane == 0) {
            // self_js - cross_js = softplus(-dC) - softplus(-dS)  (LOG2 cancels)
            float t = softplusf(-dC) - softplusf(-dS);
            acc += (double)t * (double)t;
        }
    }

    __shared__ double sh[WARPS_PER_BLOCK];
    __shared__ int    s_isLast;
    if (lane == 0) sh[wib] = acc;
    __syncthreads();

    if (threadIdx.x == 0) {
        double s = 0.0;
        #pragma unroll
        for (int i = 0; i < WARPS_PER_BLOCK; i++) s += sh[i];
        g_part[blockIdx.x] = s;
        __threadfence();
        unsigned int old = atomicAdd(&g_count, 1u);
        s_isLast = (old == gridDim.x - 1) ? 1 : 0;
    }
    __syncthreads();

    if (s_isLast) {
        // Last block: reduce all partials, split by stream (first half = stream 0).
        const int grid = gridDim.x;
        const int half = grid >> 1;
        double s0 = 0.0, s1 = 0.0;
        volatile double* vp = g_part;
        for (int i = threadIdx.x; i < grid; i += THREADS) {
            double v = vp[i];
            if (i < half) s0 += v; else s1 += v;
        }
        // warp reduce
        #pragma unroll
        for (int off = 16; off > 0; off >>= 1) {
            s0 += __shfl_xor_sync(0xFFFFFFFFu, s0, off);
            s1 += __shfl_xor_sync(0xFFFFFFFFu, s1, off);
        }
        __shared__ double r0[WARPS_PER_BLOCK], r1[WARPS_PER_BLOCK];
        if (lane == 0) { r0[wib] = s0; r1[wib] = s1; }
        __syncthreads();
        if (threadIdx.x == 0) {
            double S0 = 0.0, S1 = 0.0;
            #pragma unroll
            for (int i = 0; i < WARPS_PER_BLOCK; i++) { S0 += r0[i]; S1 += r1[i]; }
            out[0] = (float)(sqrt(S0) + sqrt(S1));
            atomicExch(&g_count, 0u);   // reset for next graph replay
        }
    }
}

extern "C" void kernel_launch(void* const* d_in, const int* in_sizes, int n_in,
                              void* d_out, int out_size) {
    const int*   b1 = (const int*)d_in[0];
    const int*   b2 = (const int*)d_in[1];
    const float* z1 = (const float*)d_in[2];
    const float* z2 = (const float*)d_in[3];
    const float* g1 = (const float*)d_in[4];
    const float* g2 = (const float*)d_in[5];
    float* out = (float*)d_out;

    const int N = in_sizes[0];                         // 65536
    const int rowsPerBlock = ROWS_PER_WARP * WARPS_PER_BLOCK;  // 128
    const int grid = (2 * N) / rowsPerBlock;           // 1024

    sat_fused_kernel<<<grid, THREADS>>>(b1, b2, z1, z2, g1, g2, out, N);
}